// round 5
// baseline (speedup 1.0000x reference)
#include <cuda_runtime.h>
#include <cuda_bf16.h>
#include <cstdint>

// Problem constants: N=50000 nodes, E=800000 edges, IN_DIM=256,
// HEADS=4, HID=64 -> out dim 256.
#define MAXN 50000
#define MAXE 800000
#define MAXT (MAXE + MAXN)

#define DIM 256
#define NEG_SLOPE 0.2f

// ------------------------- device scratch -------------------------
__device__ float  g_h[(size_t)MAXN * DIM];   // projected features [N,256]
__device__ float4 g_asrc[MAXN];              // per-node src logits [N,4]
__device__ float4 g_adst[MAXN];              // per-node dst logits [N,4]
__device__ float4 g_denom[MAXN];             // softmax denominators [N,4]
__device__ float4 g_num[MAXT];               // exp(e) per edge [T,4]
__device__ int    g_idx_stride;              // 1 = int32 indices, 2 = int64 (low word)

// ------------------------- helpers -------------------------
__device__ __forceinline__ void red_add_v4(float4* addr, float4 v) {
    asm volatile("red.global.add.v4.f32 [%0], {%1,%2,%3,%4};"
                 :: "l"(addr), "f"(v.x), "f"(v.y), "f"(v.z), "f"(v.w)
                 : "memory");
}

// ------------------------- 0) dtype detection -------------------------
// JAX may silently downcast the reference's int64 edge_index to int32.
// Little-endian int64 with values < 2^31 => every odd 32-bit word is 0.
// Random int32 node indices => odd words almost surely nonzero somewhere.
__global__ void detect_idx_kernel(const int* __restrict__ ei32, int E)
{
    __shared__ int s_nonzero;
    if (threadIdx.x == 0) s_nonzero = 0;
    __syncthreads();
    int nz = 0;
    int samples = (E < 4096) ? E : 4096;
    for (int i = threadIdx.x; i < samples; i += blockDim.x)
        nz |= ei32[2 * i + 1];
    if (nz) atomicOr(&s_nonzero, 1);
    __syncthreads();
    if (threadIdx.x == 0)
        g_idx_stride = s_nonzero ? 1 : 2;   // nonzero odd word -> int32
}

__device__ __forceinline__ void load_edge(const int* __restrict__ ei32,
                                          int t, int E, int stride,
                                          int& s, int& d)
{
    // stride==1: int32 layout [src(E), dst(E)]
    // stride==2: int64 layout, take low words: src at 2t, dst at 2(E+t)
    s = ei32[(size_t)t * stride];
    d = ei32[((size_t)E + t) * stride];
}

// ------------------------- 1) SGEMM: g_h = x @ W -------------------------
#define BM 128
#define BN 128
#define BK 8
#define TM 8
#define TN 8

__global__ __launch_bounds__(256)
void sgemm_kernel(const float* __restrict__ A,   // x  [M,256]
                  const float* __restrict__ B,   // W  [256,256]
                  int M)
{
    const int K = DIM, N = DIM;
    __shared__ float As[BK][BM];
    __shared__ float Bs[BK][BN];

    int tid  = threadIdx.x;
    int brow = blockIdx.x * BM;
    int bcol = blockIdx.y * BN;

    int aRow = tid >> 1;
    int aCol = (tid & 1) << 2;
    int bRow = tid >> 5;
    int bCol = (tid & 31) << 2;

    int ty = tid >> 4;
    int tx = tid & 15;

    float acc[TM][TN];
    #pragma unroll
    for (int i = 0; i < TM; i++)
        #pragma unroll
        for (int j = 0; j < TN; j++) acc[i][j] = 0.f;

    const float* Aptr = A + (size_t)(brow + aRow) * K + aCol;
    const float* Bptr = B + (size_t)bRow * N + bcol + bCol;
    bool aValid = (brow + aRow) < M;

    for (int k0 = 0; k0 < K; k0 += BK) {
        float4 av = aValid ? *(const float4*)Aptr : make_float4(0.f, 0.f, 0.f, 0.f);
        float4 bv = *(const float4*)Bptr;
        As[aCol + 0][aRow] = av.x;
        As[aCol + 1][aRow] = av.y;
        As[aCol + 2][aRow] = av.z;
        As[aCol + 3][aRow] = av.w;
        *(float4*)&Bs[bRow][bCol] = bv;
        __syncthreads();

        #pragma unroll
        for (int kk = 0; kk < BK; kk++) {
            float ra[TM], rb[TN];
            #pragma unroll
            for (int i = 0; i < TM; i++) ra[i] = As[kk][ty * TM + i];
            #pragma unroll
            for (int j = 0; j < TN; j++) rb[j] = Bs[kk][tx * TN + j];
            #pragma unroll
            for (int i = 0; i < TM; i++)
                #pragma unroll
                for (int j = 0; j < TN; j++)
                    acc[i][j] = fmaf(ra[i], rb[j], acc[i][j]);
        }
        __syncthreads();
        Aptr += BK;
        Bptr += BK * N;
    }

    #pragma unroll
    for (int i = 0; i < TM; i++) {
        int r = brow + ty * TM + i;
        if (r < M) {
            float* crow = g_h + (size_t)r * N + bcol + tx * TN;
            *(float4*)(crow)     = make_float4(acc[i][0], acc[i][1], acc[i][2], acc[i][3]);
            *(float4*)(crow + 4) = make_float4(acc[i][4], acc[i][5], acc[i][6], acc[i][7]);
        }
    }
}

// ------------------------- 2) per-node logits -------------------------
__global__ __launch_bounds__(256)
void attn_logits_kernel(const float* __restrict__ att_src,
                        const float* __restrict__ att_dst,
                        int N)
{
    int g    = blockIdx.x * blockDim.x + threadIdx.x;
    int node = g >> 5;
    int lane = threadIdx.x & 31;
    if (node >= N) return;

    const float4* row = (const float4*)(g_h + (size_t)node * DIM);
    const float4* as4 = (const float4*)att_src;
    const float4* ad4 = (const float4*)att_dst;

    float4 h0 = row[lane],  h1 = row[lane + 32];
    float4 s0v = as4[lane], s1v = as4[lane + 32];
    float4 d0v = ad4[lane], d1v = ad4[lane + 32];

    float s0 = h0.x * s0v.x + h0.y * s0v.y + h0.z * s0v.z + h0.w * s0v.w;
    float d0 = h0.x * d0v.x + h0.y * d0v.y + h0.z * d0v.z + h0.w * d0v.w;
    float s1 = h1.x * s1v.x + h1.y * s1v.y + h1.z * s1v.z + h1.w * s1v.w;
    float d1 = h1.x * d1v.x + h1.y * d1v.y + h1.z * d1v.z + h1.w * d1v.w;

    // lanes 0-15 cover head 0 (h0) & head 2 (h1); lanes 16-31 head 1 & head 3
    #pragma unroll
    for (int off = 8; off; off >>= 1) {
        s0 += __shfl_down_sync(0xffffffffu, s0, off, 16);
        d0 += __shfl_down_sync(0xffffffffu, d0, off, 16);
        s1 += __shfl_down_sync(0xffffffffu, s1, off, 16);
        d1 += __shfl_down_sync(0xffffffffu, d1, off, 16);
    }
    if ((lane & 15) == 0) {
        int hgrp = lane >> 4;  // 0 or 1
        float* ap = (float*)(g_asrc + node);
        float* dp = (float*)(g_adst + node);
        ap[hgrp] = s0;  ap[hgrp + 2] = s1;
        dp[hgrp] = d0;  dp[hgrp + 2] = d1;
    }
}

// ------------------------- 3) init: out = bias, denom = 0 ----------------
__global__ void init_kernel(float4* __restrict__ out,
                            const float4* __restrict__ bias4, int N)
{
    int i  = blockIdx.x * blockDim.x + threadIdx.x;
    int n4 = N * (DIM / 4);
    if (i < n4) out[i] = bias4[i & 63];
    if (i < N)  g_denom[i] = make_float4(0.f, 0.f, 0.f, 0.f);
}

// ------------------------- 4) edge logits + denom -------------------------
__global__ __launch_bounds__(256)
void edge_logits_kernel(const int* __restrict__ ei32, int E, int T)
{
    int t = blockIdx.x * blockDim.x + threadIdx.x;
    if (t >= T) return;
    int stride = g_idx_stride;
    int s, d;
    if (t < E) load_edge(ei32, t, E, stride, s, d);
    else       s = d = t - E;   // self loop

    float4 a = g_asrc[s];
    float4 b = g_adst[d];
    float4 e;
    e.x = a.x + b.x; e.y = a.y + b.y; e.z = a.z + b.z; e.w = a.w + b.w;
    e.x = e.x > 0.f ? e.x : NEG_SLOPE * e.x;
    e.y = e.y > 0.f ? e.y : NEG_SLOPE * e.y;
    e.z = e.z > 0.f ? e.z : NEG_SLOPE * e.z;
    e.w = e.w > 0.f ? e.w : NEG_SLOPE * e.w;
    // max-shift unnecessary: |e| small, exp fp32-safe, shift cancels in num/denom
    float4 nm = make_float4(expf(e.x), expf(e.y), expf(e.z), expf(e.w));
    g_num[t] = nm;
    red_add_v4(&g_denom[d], nm);
}

// ------------------------- 5) weighted scatter -------------------------
// One warp per edge: out[dst] += (num/denom) * h[src], 64 float4 per edge.
__global__ __launch_bounds__(256)
void edge_scatter_kernel(const int* __restrict__ ei32, int E, int T,
                         float4* __restrict__ out)
{
    int g    = blockIdx.x * blockDim.x + threadIdx.x;
    int edge = g >> 5;
    int lane = threadIdx.x & 31;
    if (edge >= T) return;

    int stride = g_idx_stride;
    int s, d;
    if (edge < E) load_edge(ei32, edge, E, stride, s, d);
    else          s = d = edge - E;

    float4 nm = g_num[edge];
    float4 dn = g_denom[d];
    // float4 index `lane`: head = lane/16 for first half, +2 for second half
    float w01 = (lane < 16) ? (nm.x / dn.x) : (nm.y / dn.y);
    float w23 = (lane < 16) ? (nm.z / dn.z) : (nm.w / dn.w);

    const float4* hrow = (const float4*)(g_h + (size_t)s * DIM);
    float4* orow = out + (size_t)d * (DIM / 4);

    float4 v0 = hrow[lane];
    v0.x *= w01; v0.y *= w01; v0.z *= w01; v0.w *= w01;
    red_add_v4(orow + lane, v0);

    float4 v1 = hrow[lane + 32];
    v1.x *= w23; v1.y *= w23; v1.z *= w23; v1.w *= w23;
    red_add_v4(orow + lane + 32, v1);
}

// ------------------------- 6) ReLU -------------------------
__global__ void relu_kernel(float4* __restrict__ out, int n4)
{
    int i = blockIdx.x * blockDim.x + threadIdx.x;
    if (i < n4) {
        float4 v = out[i];
        v.x = fmaxf(v.x, 0.f); v.y = fmaxf(v.y, 0.f);
        v.z = fmaxf(v.z, 0.f); v.w = fmaxf(v.w, 0.f);
        out[i] = v;
    }
}

// ------------------------- launch -------------------------
extern "C" void kernel_launch(void* const* d_in, const int* in_sizes, int n_in,
                              void* d_out, int out_size)
{
    const float* x       = (const float*)d_in[0];   // [N,256] f32
    const int*   ei32    = (const int*)d_in[1];     // [2,E] int32 OR int64 (detected)
    const float* W       = (const float*)d_in[2];   // [256,256]
    const float* att_src = (const float*)d_in[3];   // [4,64]
    const float* att_dst = (const float*)d_in[4];   // [4,64]
    const float* bias    = (const float*)d_in[5];   // [256]

    int N = in_sizes[0] / DIM;   // 50000
    int E = in_sizes[1] / 2;     // 800000
    int T = E + N;
    float* out = (float*)d_out;
    int n4 = N * (DIM / 4);

    // 0) detect edge_index dtype (int32 vs int64)
    detect_idx_kernel<<<1, 256>>>(ei32, E);

    // 1) h = x @ W
    dim3 gg((N + BM - 1) / BM, DIM / BN);
    sgemm_kernel<<<gg, 256>>>(x, W, N);

    // 2) per-node attention logits (warp per node)
    attn_logits_kernel<<<(N * 32 + 255) / 256, 256>>>(att_src, att_dst, N);

    // 3) out = bias, denom = 0
    init_kernel<<<(n4 + 255) / 256, 256>>>((float4*)out, (const float4*)bias, N);

    // 4) edge softmax numerators + denominator scatter
    edge_logits_kernel<<<(T + 255) / 256, 256>>>(ei32, E, T);

    // 5) out[dst] += alpha * h[src]  (warp per edge)
    long long threads = (long long)T * 32;
    edge_scatter_kernel<<<(int)((threads + 255) / 256), 256>>>(ei32, E, T, (float4*)out);

    // 6) ReLU
    relu_kernel<<<(n4 + 255) / 256, 256>>>((float4*)out, n4);
}

// round 9
// speedup vs baseline: 1.8101x; 1.8101x over previous
#include <cuda_runtime.h>
#include <cuda_bf16.h>
#include <cstdint>

// N=50000 nodes, E=800000 edges, IN_DIM=256, HEADS=4, HID=64 -> out 256.
#define MAXN 50000
#define MAXE 800000
#define MAXT (MAXE + MAXN)
#define DIM 256
#define NEG_SLOPE 0.2f

// ------------------------- device scratch -------------------------
__device__ float          g_h[(size_t)MAXN * DIM];     // projected features fp32
__device__ __nv_bfloat16  g_xhi[(size_t)MAXN * DIM];   // x split hi
__device__ __nv_bfloat16  g_xlo[(size_t)MAXN * DIM];   // x split lo
__device__ __nv_bfloat16  g_wthi[DIM * DIM];           // W^T split hi: [n][k]
__device__ __nv_bfloat16  g_wtlo[DIM * DIM];
__device__ float4 g_asrc[MAXN];
__device__ float4 g_adst[MAXN];
__device__ float4 g_denom[MAXN];
__device__ float4 g_num[MAXT];
__device__ int    g_deg[MAXN];
__device__ int    g_rowoff[MAXN];
__device__ int    g_cursor[MAXN];
__device__ int2   g_slot[MAXT];        // {src, edge_id} binned by dst
__device__ int    g_bsum[64];
__device__ int    g_bbase[64];
__device__ int    g_idx_stride;        // 1 = int32 indices, 2 = int64 low word

// ------------------------- helpers -------------------------
__device__ __forceinline__ uint32_t smem_u32(const void* p) {
    uint32_t a;
    asm("{ .reg .u64 t; cvta.to.shared.u64 t, %1; cvt.u32.u64 %0, t; }"
        : "=r"(a) : "l"(p));
    return a;
}
__device__ __forceinline__ void red_add_v4(float4* addr, float4 v) {
    asm volatile("red.global.add.v4.f32 [%0], {%1,%2,%3,%4};"
                 :: "l"(addr), "f"(v.x), "f"(v.y), "f"(v.z), "f"(v.w) : "memory");
}

// ------------------------- 0) dtype detection -------------------------
// JAX default x64-off silently makes edge_index int32; detect via odd words.
__global__ void detect_idx_kernel(const int* __restrict__ ei32, int E)
{
    __shared__ int s_nonzero;
    if (threadIdx.x == 0) s_nonzero = 0;
    __syncthreads();
    int nz = 0;
    int samples = (E < 4096) ? E : 4096;
    for (int i = threadIdx.x; i < samples; i += blockDim.x)
        nz |= ei32[2 * i + 1];
    if (nz) atomicOr(&s_nonzero, 1);
    __syncthreads();
    if (threadIdx.x == 0) g_idx_stride = s_nonzero ? 1 : 2;
}

__device__ __forceinline__ void load_edge(const int* __restrict__ ei32,
                                          int t, int E, int stride, int& s, int& d)
{
    s = ei32[(size_t)t * stride];
    d = ei32[((size_t)E + t) * stride];
}

// ------------------------- 1a) W transpose + bf16 split -------------------------
__global__ void prep_w_kernel(const float* __restrict__ W)
{
    int i = blockIdx.x * blockDim.x + threadIdx.x;   // i = k*256 + n
    if (i < DIM * DIM) {
        int k = i >> 8, n = i & 255;
        float w = W[i];
        __nv_bfloat16 hi = __float2bfloat16(w);
        __nv_bfloat16 lo = __float2bfloat16(w - __bfloat162float(hi));
        g_wthi[n * DIM + k] = hi;
        g_wtlo[n * DIM + k] = lo;
    }
}

// ------------------------- 1b) x bf16 split -------------------------
__global__ void split_x_kernel(const float* __restrict__ x, int total4)
{
    int i = blockIdx.x * blockDim.x + threadIdx.x;
    if (i < total4) {
        float4 v = ((const float4*)x)[i];
        __nv_bfloat16 h0 = __float2bfloat16(v.x), h1 = __float2bfloat16(v.y);
        __nv_bfloat16 h2 = __float2bfloat16(v.z), h3 = __float2bfloat16(v.w);
        __nv_bfloat16 l0 = __float2bfloat16(v.x - __bfloat162float(h0));
        __nv_bfloat16 l1 = __float2bfloat16(v.y - __bfloat162float(h1));
        __nv_bfloat16 l2 = __float2bfloat16(v.z - __bfloat162float(h2));
        __nv_bfloat16 l3 = __float2bfloat16(v.w - __bfloat162float(h3));
        ((__nv_bfloat162*)g_xhi)[2 * i]     = __halves2bfloat162(h0, h1);
        ((__nv_bfloat162*)g_xhi)[2 * i + 1] = __halves2bfloat162(h2, h3);
        ((__nv_bfloat162*)g_xlo)[2 * i]     = __halves2bfloat162(l0, l1);
        ((__nv_bfloat162*)g_xlo)[2 * i + 1] = __halves2bfloat162(l2, l3);
    }
}

// ------------------------- 2) init: denom=0, deg=0 -------------------------
__global__ void init2_kernel(int N)
{
    int i = blockIdx.x * blockDim.x + threadIdx.x;
    if (i < N) { g_denom[i] = make_float4(0.f, 0.f, 0.f, 0.f); g_deg[i] = 0; }
}

// ------------------------- 3) GEMM via mma.sync bf16x3 -------------------------
// h = x@W with error-free-ish split: hi*hi + lo*hi + hi*lo, fp32 accumulate.
// NOTE: tcgen05 is compile-blocked (harness lowers via compute_103 PTX, no 'a'
// feature), so we use baseline-PTX HMMA mma.sync.m16n8k16.
// CTA tile 64(M) x 256(N), BK=64, 8 warps (2x4), warp tile 32x64.
#define GBM 64
#define GBK 64
#define ASTR 72   // bf16 stride with +8 pad -> ldmatrix conflict-free

__global__ __launch_bounds__(256)
void gemm_mma_kernel(int M)
{
    __shared__ __align__(16) __nv_bfloat16 As[GBM * ASTR];   //  9216 B
    __shared__ __align__(16) __nv_bfloat16 Bs[DIM * ASTR];   // 36864 B

    int tid = threadIdx.x, lane = tid & 31, wid = tid >> 5;
    int warp_m = wid & 1;        // 0..1
    int warp_n = wid >> 1;       // 0..3
    int brow = blockIdx.x * GBM;

    float acc[2][8][4];
    #pragma unroll
    for (int mi = 0; mi < 2; mi++)
        #pragma unroll
        for (int ni = 0; ni < 8; ni++)
            #pragma unroll
            for (int q = 0; q < 4; q++) acc[mi][ni][q] = 0.f;

    uint32_t As_a = smem_u32(As);
    uint32_t Bs_a = smem_u32(Bs);

    // ldmatrix lane address components
    int a_row = warp_m * 32 + (lane & 15);      // + mi*16
    int a_k   = (lane >> 4) << 3;               // 0 or 8, + ks*16
    int b_row = warp_n * 64 + (lane & 7);       // + ni*8
    int b_k   = ((lane >> 3) & 1) << 3;         // 0 or 8, + ks*16

    for (int it = 0; it < 12; it++) {
        int pass = it >> 2, kc = it & 3;
        const __nv_bfloat16* ap = (pass == 1) ? g_xlo  : g_xhi;
        const __nv_bfloat16* bp = (pass == 2) ? g_wtlo : g_wthi;

        __syncthreads();   // previous iter's reads done
        // A: 64 rows x 64 bf16 = 512 uint4, 2 per thread
        #pragma unroll
        for (int i = 0; i < 2; i++) {
            int idx = tid + i * 256;
            int r = idx >> 3, c = (idx & 7) << 3;
            uint4 v = make_uint4(0u, 0u, 0u, 0u);
            if (brow + r < M)
                v = *(const uint4*)(ap + (size_t)(brow + r) * DIM + kc * GBK + c);
            *(uint4*)&As[r * ASTR + c] = v;
        }
        // B: 256 rows x 64 bf16 = 2048 uint4, 8 per thread
        #pragma unroll
        for (int i = 0; i < 8; i++) {
            int idx = tid + i * 256;
            int r = idx >> 3, c = (idx & 7) << 3;
            uint4 v = *(const uint4*)(bp + (size_t)r * DIM + kc * GBK + c);
            *(uint4*)&Bs[r * ASTR + c] = v;
        }
        __syncthreads();

        #pragma unroll
        for (int ks = 0; ks < 4; ks++) {
            uint32_t a_frag[2][4];
            #pragma unroll
            for (int mi = 0; mi < 2; mi++) {
                uint32_t addr = As_a +
                    (uint32_t)(((a_row + mi * 16) * ASTR + ks * 16 + a_k) * 2);
                asm volatile(
                    "ldmatrix.sync.aligned.m8n8.x4.shared.b16 {%0,%1,%2,%3}, [%4];"
                    : "=r"(a_frag[mi][0]), "=r"(a_frag[mi][1]),
                      "=r"(a_frag[mi][2]), "=r"(a_frag[mi][3])
                    : "r"(addr));
            }
            #pragma unroll
            for (int ni = 0; ni < 8; ni++) {
                uint32_t b0, b1;
                uint32_t addr = Bs_a +
                    (uint32_t)(((b_row + ni * 8) * ASTR + ks * 16 + b_k) * 2);
                asm volatile(
                    "ldmatrix.sync.aligned.m8n8.x2.shared.b16 {%0,%1}, [%2];"
                    : "=r"(b0), "=r"(b1) : "r"(addr));
                #pragma unroll
                for (int mi = 0; mi < 2; mi++) {
                    asm volatile(
                        "mma.sync.aligned.m16n8k16.row.col.f32.bf16.bf16.f32 "
                        "{%0,%1,%2,%3}, {%4,%5,%6,%7}, {%8,%9}, {%0,%1,%2,%3};"
                        : "+f"(acc[mi][ni][0]), "+f"(acc[mi][ni][1]),
                          "+f"(acc[mi][ni][2]), "+f"(acc[mi][ni][3])
                        : "r"(a_frag[mi][0]), "r"(a_frag[mi][1]),
                          "r"(a_frag[mi][2]), "r"(a_frag[mi][3]),
                          "r"(b0), "r"(b1));
                }
            }
        }
    }

    // Epilogue: acc -> g_h. Row = lane>>2 (+8), col pair = (lane&3)*2.
    #pragma unroll
    for (int mi = 0; mi < 2; mi++) {
        int r0 = brow + warp_m * 32 + mi * 16 + (lane >> 2);
        #pragma unroll
        for (int ni = 0; ni < 8; ni++) {
            int col = warp_n * 64 + ni * 8 + (lane & 3) * 2;
            if (r0 < M)
                *(float2*)(g_h + (size_t)r0 * DIM + col) =
                    make_float2(acc[mi][ni][0], acc[mi][ni][1]);
            if (r0 + 8 < M)
                *(float2*)(g_h + (size_t)(r0 + 8) * DIM + col) =
                    make_float2(acc[mi][ni][2], acc[mi][ni][3]);
        }
    }
}

// ------------------------- 4) per-node attention logits -------------------------
__global__ __launch_bounds__(256)
void attn_logits_kernel(const float* __restrict__ att_src,
                        const float* __restrict__ att_dst, int N)
{
    int g    = blockIdx.x * blockDim.x + threadIdx.x;
    int node = g >> 5;
    int lane = threadIdx.x & 31;
    if (node >= N) return;

    const float4* row = (const float4*)(g_h + (size_t)node * DIM);
    const float4* as4 = (const float4*)att_src;
    const float4* ad4 = (const float4*)att_dst;

    float4 h0 = row[lane],  h1 = row[lane + 32];
    float4 s0v = as4[lane], s1v = as4[lane + 32];
    float4 d0v = ad4[lane], d1v = ad4[lane + 32];

    float s0 = h0.x * s0v.x + h0.y * s0v.y + h0.z * s0v.z + h0.w * s0v.w;
    float d0 = h0.x * d0v.x + h0.y * d0v.y + h0.z * d0v.z + h0.w * d0v.w;
    float s1 = h1.x * s1v.x + h1.y * s1v.y + h1.z * s1v.z + h1.w * s1v.w;
    float d1 = h1.x * d1v.x + h1.y * d1v.y + h1.z * d1v.z + h1.w * d1v.w;

    #pragma unroll
    for (int off = 8; off; off >>= 1) {
        s0 += __shfl_down_sync(0xffffffffu, s0, off, 16);
        d0 += __shfl_down_sync(0xffffffffu, d0, off, 16);
        s1 += __shfl_down_sync(0xffffffffu, s1, off, 16);
        d1 += __shfl_down_sync(0xffffffffu, d1, off, 16);
    }
    if ((lane & 15) == 0) {
        int hgrp = lane >> 4;  // 0 or 1
        float* ap = (float*)&g_asrc[node];
        float* dp = (float*)&g_adst[node];
        ap[hgrp] = s0;  ap[hgrp + 2] = s1;
        dp[hgrp] = d0;  dp[hgrp + 2] = d1;
    }
}

// ------------------------- 5) edge logits + denom + deg -------------------------
__global__ __launch_bounds__(256)
void edge_logits_kernel(const int* __restrict__ ei32, int E, int T)
{
    int t = blockIdx.x * blockDim.x + threadIdx.x;
    if (t >= T) return;
    int stride = g_idx_stride;
    int s, d;
    if (t < E) load_edge(ei32, t, E, stride, s, d);
    else       s = d = t - E;

    float4 a = g_asrc[s];
    float4 b = g_adst[d];
    float4 e = make_float4(a.x + b.x, a.y + b.y, a.z + b.z, a.w + b.w);
    e.x = e.x > 0.f ? e.x : NEG_SLOPE * e.x;
    e.y = e.y > 0.f ? e.y : NEG_SLOPE * e.y;
    e.z = e.z > 0.f ? e.z : NEG_SLOPE * e.z;
    e.w = e.w > 0.f ? e.w : NEG_SLOPE * e.w;
    // max-shift unnecessary: |e| small, exp fp32-safe, shift cancels in num/denom
    float4 nm = make_float4(expf(e.x), expf(e.y), expf(e.z), expf(e.w));
    g_num[t] = nm;
    red_add_v4(&g_denom[d], nm);
    atomicAdd(&g_deg[d], 1);
}

// ------------------------- 6) CSR build: scan + fill -------------------------
__global__ void scan1_kernel(int N)
{
    __shared__ int sh[1024];
    int i = blockIdx.x * 1024 + threadIdx.x;
    int v = (i < N) ? g_deg[i] : 0;
    sh[threadIdx.x] = v;
    __syncthreads();
    #pragma unroll
    for (int off = 1; off < 1024; off <<= 1) {
        int t = (threadIdx.x >= off) ? sh[threadIdx.x - off] : 0;
        __syncthreads();
        sh[threadIdx.x] += t;
        __syncthreads();
    }
    if (i < N) g_rowoff[i] = sh[threadIdx.x] - v;   // exclusive within block
    if (threadIdx.x == 1023) g_bsum[blockIdx.x] = sh[1023];
}

__global__ void scan2_kernel(int nb)
{
    if (threadIdx.x == 0) {
        int run = 0;
        for (int b = 0; b < nb; b++) { g_bbase[b] = run; run += g_bsum[b]; }
    }
}

__global__ void scan3_kernel(int N)
{
    int i = blockIdx.x * blockDim.x + threadIdx.x;
    if (i < N) {
        int o = g_rowoff[i] + g_bbase[i >> 10];
        g_rowoff[i] = o;
        g_cursor[i] = o;
    }
}

__global__ void fill_kernel(const int* __restrict__ ei32, int E, int T)
{
    int t = blockIdx.x * blockDim.x + threadIdx.x;
    if (t >= T) return;
    int stride = g_idx_stride;
    int s, d;
    if (t < E) load_edge(ei32, t, E, stride, s, d);
    else       s = d = t - E;
    int pos = atomicAdd(&g_cursor[d], 1);
    g_slot[pos] = make_int2(s, t);
}

// ------------------------- 7) aggregate (warp/node) + bias + ReLU -------------
__global__ __launch_bounds__(256)
void aggregate_kernel(float* __restrict__ out, const float* __restrict__ bias, int N)
{
    int g    = blockIdx.x * blockDim.x + threadIdx.x;
    int node = g >> 5;
    int lane = threadIdx.x & 31;
    if (node >= N) return;

    int off = g_rowoff[node];
    int deg = g_deg[node];
    float4 dn  = g_denom[node];
    float4 inv = make_float4(1.f / dn.x, 1.f / dn.y, 1.f / dn.z, 1.f / dn.w);

    float4 a0 = make_float4(0.f, 0.f, 0.f, 0.f);
    float4 a1 = make_float4(0.f, 0.f, 0.f, 0.f);

    for (int e = 0; e < deg; e++) {
        int2 sl = g_slot[off + e];
        float4 nm = g_num[sl.y];
        float w01 = (lane < 16) ? nm.x * inv.x : nm.y * inv.y;  // heads 0/1
        float w23 = (lane < 16) ? nm.z * inv.z : nm.w * inv.w;  // heads 2/3
        const float4* hr = (const float4*)(g_h + (size_t)sl.x * DIM);
        float4 v0 = hr[lane];
        float4 v1 = hr[lane + 32];
        a0.x = fmaf(w01, v0.x, a0.x); a0.y = fmaf(w01, v0.y, a0.y);
        a0.z = fmaf(w01, v0.z, a0.z); a0.w = fmaf(w01, v0.w, a0.w);
        a1.x = fmaf(w23, v1.x, a1.x); a1.y = fmaf(w23, v1.y, a1.y);
        a1.z = fmaf(w23, v1.z, a1.z); a1.w = fmaf(w23, v1.w, a1.w);
    }

    const float4* b4 = (const float4*)bias;
    float4 bb0 = b4[lane], bb1 = b4[lane + 32];
    a0.x = fmaxf(a0.x + bb0.x, 0.f); a0.y = fmaxf(a0.y + bb0.y, 0.f);
    a0.z = fmaxf(a0.z + bb0.z, 0.f); a0.w = fmaxf(a0.w + bb0.w, 0.f);
    a1.x = fmaxf(a1.x + bb1.x, 0.f); a1.y = fmaxf(a1.y + bb1.y, 0.f);
    a1.z = fmaxf(a1.z + bb1.z, 0.f); a1.w = fmaxf(a1.w + bb1.w, 0.f);

    float4* orow = (float4*)(out + (size_t)node * DIM);
    orow[lane]      = a0;
    orow[lane + 32] = a1;
}

// ------------------------- launch -------------------------
extern "C" void kernel_launch(void* const* d_in, const int* in_sizes, int n_in,
                              void* d_out, int out_size)
{
    const float* x       = (const float*)d_in[0];
    const int*   ei32    = (const int*)d_in[1];
    const float* W       = (const float*)d_in[2];
    const float* att_src = (const float*)d_in[3];
    const float* att_dst = (const float*)d_in[4];
    const float* bias    = (const float*)d_in[5];

    int N = in_sizes[0] / DIM;   // 50000
    int E = in_sizes[1] / 2;     // 800000
    int T = E + N;
    float* out = (float*)d_out;

    // 0) edge index dtype
    detect_idx_kernel<<<1, 256>>>(ei32, E);

    // 1) bf16 splits of W^T and x
    prep_w_kernel<<<(DIM * DIM + 255) / 256, 256>>>(W);
    split_x_kernel<<<(N * DIM / 4 + 255) / 256, 256>>>(x, N * DIM / 4);

    // 2) zero denom/deg
    init2_kernel<<<(N + 255) / 256, 256>>>(N);

    // 3) tensor-core GEMM (mma.sync bf16x3)
    gemm_mma_kernel<<<(N + GBM - 1) / GBM, 256>>>(N);

    // 4) per-node attention logits
    attn_logits_kernel<<<(N * 32 + 255) / 256, 256>>>(att_src, att_dst, N);

    // 5) edge softmax numerators + denom + degree
    edge_logits_kernel<<<(T + 255) / 256, 256>>>(ei32, E, T);

    // 6) CSR build
    int nb = (N + 1023) / 1024;
    scan1_kernel<<<nb, 1024>>>(N);
    scan2_kernel<<<1, 32>>>(nb);
    scan3_kernel<<<(N + 255) / 256, 256>>>(N);
    fill_kernel<<<(T + 255) / 256, 256>>>(ei32, E, T);

    // 7) per-node aggregation + bias + ReLU
    aggregate_kernel<<<(N * 32 + 255) / 256, 256>>>(out, bias, N);
}